// round 10
// baseline (speedup 1.0000x reference)
#include <cuda_runtime.h>
#include <math.h>
#include <cstdint>
#include <mma.h>

using namespace nvcuda;

#define Bsz 2
#define DIM 192
#define Dd 16
#define Hh 32
#define Ww 32
#define HW 1024
#define DHW 16384
#define EPSV 1e-5f

// ---------------- scratch (device globals; no allocations allowed) ----------------
__device__ float g_k  [Bsz * DIM * DHW];     // key conv output (post BN+ReLU)
__device__ float g_e  [Bsz * 96  * DHW];     // embed 1
__device__ float g_w  [Bsz * 216 * DHW];     // dyn weights pre-GN (biased)
__device__ float g_v  [Bsz * DIM * DHW];     // value conv output
__device__ float g_x2 [Bsz * DIM * DHW];     // aggregated + swish
__device__ float g_stats[Bsz * 24 * 2];      // per (b, gn-group): mean, rstd
__device__ float g_part [Bsz * 24 * 8 * 2];  // partial sums (deterministic 2-stage)
__device__ float g_gap[Bsz * DIM];
__device__ float g_attn[Bsz * DIM * 2];
// pre-transposed tf32 weights (accessed ONLY from device code!)
__device__ float g_wconv[4 * 27 * 48 * 48];  // [g][tap][ci][co]
__device__ float g_we1t[384 * 96];           // [i][o]
__device__ float g_we2t[96 * 224];           // [i][o] (216 padded to 224 w/ zeros)
__device__ float g_wc1t[192 * 192];          // [i][o]

// ================= helpers =================
__device__ __forceinline__ float f2tf(float f) {
    uint32_t u;
    asm("cvt.rna.tf32.f32 %0, %1;" : "=r"(u) : "f"(f));
    return __uint_as_float(u);
}

// ================= prep kernels: transpose + tf32-convert weights =================
__global__ __launch_bounds__(256) void k_prep_gemm(
    const float* __restrict__ w_e1, const float* __restrict__ w_e2,
    const float* __restrict__ w_c1)
{
    int id = blockIdx.x * 256 + threadIdx.x;
    if (id < 36864) {
        int i = id / 96, o = id % 96;
        g_we1t[id] = f2tf(w_e1[o * 384 + i]);
    } else if (id < 36864 + 21504) {
        int r = id - 36864;
        int i = r / 224, o = r % 224;
        g_we2t[r] = (o < 216) ? f2tf(w_e2[o * 96 + i]) : 0.f;
    } else if (id < 36864 + 21504 + 36864) {
        int r = id - 36864 - 21504;
        int i = r / 192, o = r % 192;
        g_wc1t[r] = f2tf(w_c1[o * 192 + i]);
    }
}
__global__ __launch_bounds__(256) void k_prep_conv(const float* __restrict__ w_key)
{
    int id = blockIdx.x * 256 + threadIdx.x;
    if (id < 248832) {
        int co = id % 48;
        int ci = (id / 48) % 48;
        int tap = (id / 2304) % 27;
        int g = id / 62208;
        g_wconv[id] = f2tf(w_key[((size_t)(g * 48 + co) * 48 + ci) * 27 + tap]);
    }
}

// ================= conv 3x3x3 grouped, implicit GEMM via wmma tf32 =================
// block: 256 thr = 8 warps; tile 256 pos (8y x 32x at one z) x 48 co.
// warp w owns m-tiles {2w, 2w+1} (16 pos each) x all 3 n-tiles of 16 co.
// v2: all-27-tap weight staging (2 syncs/ci-chunk), strength-reduced halo
//     staging, dynamic smem 81.4 KB.
#define HSTR 1032   // halo ci-stride in floats (mod 32 == 8)
#define WSTR 56     // weight ci-stride (mod 32 == 24)
__global__ __launch_bounds__(256, 2) void k_conv_mma(
    const float* __restrict__ x, const float* __restrict__ s1,
    const float* __restrict__ b1)
{
    extern __shared__ float smem[];        // 8*HSTR + 27*8*WSTR floats
    float* hs = smem;                      // 8256 floats
    float* ws = smem + 8 * HSTR;           // 12096 floats

    const int tid = threadIdx.x;
    const int lane = tid & 31, warp = tid >> 5;
    const int bz = blockIdx.z;
    const int b = bz >> 2, g = bz & 3;
    const int z = blockIdx.y;
    const int y0 = blockIdx.x * 8;

    wmma::fragment<wmma::accumulator, 16, 16, 8, float> acc[2][3];
#pragma unroll
    for (int mt = 0; mt < 2; mt++)
#pragma unroll
        for (int j = 0; j < 3; j++) wmma::fill_fragment(acc[mt][j], 0.f);

    const float* xg = x + (size_t)(b * DIM + g * 48) * DHW;
    const float* wg = g_wconv + (size_t)g * 27 * 48 * 48;

    for (int ci0 = 0; ci0 < 48; ci0 += 8) {
        __syncthreads();
        // ---- stage halo: 240 rows (8ci x 3zz x 10yy) of 34 cols; warp = row ----
        for (int R = warp; R < 240; R += 8) {
            int ci = R / 30;
            int r2 = R - ci * 30;
            int zz = r2 / 10, yy = r2 - zz * 10;
            int gz = z - 1 + zz, gy = y0 - 1 + yy;
            bool rowok = ((unsigned)gz < (unsigned)Dd) & ((unsigned)gy < (unsigned)Hh);
            const float* src = xg + (size_t)(ci0 + ci) * DHW + gz * HW + gy * Ww;
            float* dst = hs + ci * HSTR + zz * 340 + yy * 34;
            int gx = lane - 1;
            float v = (rowok && (unsigned)gx < (unsigned)Ww) ? src[gx] : 0.f;
            dst[lane] = f2tf(v);
            if (lane < 2) {
                int gx2 = 31 + lane;
                float v2 = (rowok && (unsigned)gx2 < (unsigned)Ww) ? src[gx2] : 0.f;
                dst[32 + lane] = f2tf(v2);
            }
        }
        // ---- stage ALL 27 taps of weights for this ci-chunk: [tap][ci][co] ----
        for (int idx = tid; idx < 27 * 8 * 48; idx += 256) {
            int t = idx / 384; int r = idx - t * 384;
            int ci = r / 48, co = r - ci * 48;
            ws[t * (8 * WSTR) + ci * WSTR + co] =
                wg[((size_t)t * 48 + ci0 + ci) * 48 + co];
        }
        __syncthreads();

        for (int dz = 0; dz < 3; dz++) {
            const float* hz = hs + dz * 340;
            const float* wz = ws + dz * 9 * (8 * WSTR);
#pragma unroll
            for (int t9 = 0; t9 < 9; t9++) {
                const int dy = t9 / 3, dx = t9 % 3;
                wmma::fragment<wmma::matrix_b, 16, 16, 8,
                               wmma::precision::tf32, wmma::row_major> bf[3];
#pragma unroll
                for (int j = 0; j < 3; j++)
                    wmma::load_matrix_sync(bf[j], wz + t9 * (8 * WSTR) + j * 16, WSTR);
#pragma unroll
                for (int mt = 0; mt < 2; mt++) {
                    const int mtile = warp * 2 + mt;
                    const int yy = mtile >> 1, xx0 = (mtile & 1) * 16;
                    const float* aptr = hz + (yy + dy) * 34 + xx0 + dx;
                    wmma::fragment<wmma::matrix_a, 16, 16, 8,
                                   wmma::precision::tf32, wmma::col_major> af;
                    wmma::load_matrix_sync(af, aptr, HSTR);
#pragma unroll
                    for (int j = 0; j < 3; j++)
                        wmma::mma_sync(acc[mt][j], af, bf[j], acc[mt][j]);
                }
            }
        }
    }

    // ---- epilogue: stage full 256x48 tile in smem (reuse), BN+ReLU store ----
    __syncthreads();
#pragma unroll
    for (int mt = 0; mt < 2; mt++)
#pragma unroll
        for (int j = 0; j < 3; j++)
            wmma::store_matrix_sync(smem + (warp * 32 + mt * 16) * 48 + j * 16,
                                    acc[mt][j], 48, wmma::mem_row_major);
    __syncthreads();
    for (int i = tid; i < 12288; i += 256) {
        int ch = i >> 8, pos = i & 255;
        int chg = g * 48 + ch;
        float v = smem[pos * 48 + ch] * __ldg(s1 + chg) + __ldg(b1 + chg);
        g_k[(size_t)(b * DIM + chg) * DHW + z * HW + y0 * Ww + pos] = fmaxf(v, 0.f);
    }
}

// ================= 1x1 conv GEMM via wmma tf32 =================
// D[128 pos, Opad] = A[pos, I] x Wt[I, Opad].  channel-major in/out.
// MODE 0: e = relu(bn2(.)) from concat(x, g_k), O=96,  I=384 -> g_e
// MODE 1: w = . + b_e2 from g_e,                O=216, I=96  -> g_w
// MODE 2: v = bn3(.) from x,                    O=192, I=192 -> g_v
template <int O, int Opad, int I, int MODE>
__global__ __launch_bounds__(256) void k_gemm_mma(
    const float* __restrict__ x,
    const float* __restrict__ p0, const float* __restrict__ p1)
{
    constexpr int ASTR = 136;
    constexpr int BSTR = Opad + 8;
    constexpr int NT = Opad / 32;       // n-tiles per warp
    __shared__ float As[32 * ASTR];     // also reused as epilogue patches
    __shared__ float Bs[32 * BSTR];

    const float* __restrict__ Wt =
        (MODE == 0) ? g_we1t : (MODE == 1) ? g_we2t : g_wc1t;

    const int tid = threadIdx.x;
    const int lane = tid & 31, warp = tid >> 5;
    const int mw = warp & 3, nw = warp >> 2;
    const int b = blockIdx.y;
    const int pbase = blockIdx.x * 128;

    wmma::fragment<wmma::accumulator, 16, 16, 8, float> acc[2][NT];
#pragma unroll
    for (int mt = 0; mt < 2; mt++)
#pragma unroll
        for (int j = 0; j < NT; j++) wmma::fill_fragment(acc[mt][j], 0.f);

    for (int i0 = 0; i0 < I; i0 += 32) {
        // stage A: 32 k x 128 pos (tf32)
#pragma unroll
        for (int r = 0; r < 4; r++) {
            int idx = tid + r * 256;
            int k = idx >> 5, p4 = idx & 31;
            int ch = i0 + k;
            const float* srow;
            if (MODE == 0)
                srow = (ch < DIM) ? x + (size_t)(b * DIM + ch) * DHW
                                  : g_k + (size_t)(b * DIM + ch - DIM) * DHW;
            else if (MODE == 1)
                srow = g_e + (size_t)(b * 96 + ch) * DHW;
            else
                srow = x + (size_t)(b * DIM + ch) * DHW;
            float4 v = *reinterpret_cast<const float4*>(srow + pbase + p4 * 4);
            float* dst = As + k * ASTR + p4 * 4;
            dst[0] = f2tf(v.x); dst[1] = f2tf(v.y);
            dst[2] = f2tf(v.z); dst[3] = f2tf(v.w);
        }
        // stage B: 32 k x Opad (already tf32)
        for (int idx = tid; idx < 32 * (Opad / 4); idx += 256) {
            int k = idx / (Opad / 4), q4 = idx - k * (Opad / 4);
            float4 wv = *reinterpret_cast<const float4*>(
                Wt + (size_t)(i0 + k) * Opad + q4 * 4);
            float* dst = Bs + k * BSTR + q4 * 4;
            dst[0] = wv.x; dst[1] = wv.y; dst[2] = wv.z; dst[3] = wv.w;
        }
        __syncthreads();
#pragma unroll
        for (int ks = 0; ks < 4; ks++) {
            wmma::fragment<wmma::matrix_a, 16, 16, 8,
                           wmma::precision::tf32, wmma::col_major> af[2];
#pragma unroll
            for (int mt = 0; mt < 2; mt++)
                wmma::load_matrix_sync(af[mt],
                    As + ks * 8 * ASTR + mw * 32 + mt * 16, ASTR);
#pragma unroll
            for (int j = 0; j < NT; j++) {
                wmma::fragment<wmma::matrix_b, 16, 16, 8,
                               wmma::precision::tf32, wmma::row_major> bf;
                wmma::load_matrix_sync(bf,
                    Bs + ks * 8 * BSTR + (nw * NT + j) * 16, BSTR);
                wmma::mma_sync(acc[0][j], af[0], bf, acc[0][j]);
                wmma::mma_sync(acc[1][j], af[1], bf, acc[1][j]);
            }
        }
        __syncthreads();
    }

    // ---- epilogue via per-warp smem patch (reuse As) ----
    float* patch = As + warp * 320;     // 16 x 20
    float* outp = (MODE == 0) ? g_e : (MODE == 1) ? g_w : g_v;
#pragma unroll
    for (int mt = 0; mt < 2; mt++)
#pragma unroll
        for (int j = 0; j < NT; j++) {
            wmma::store_matrix_sync(patch, acc[mt][j], 20, wmma::mem_row_major);
            __syncwarp();
            int pos0 = pbase + mw * 32 + mt * 16;
            int o0 = (nw * NT + j) * 16;
            int po = lane & 15, half = lane >> 4;
#pragma unroll
            for (int p = 0; p < 8; p++) {
                int c = p * 2 + half;
                int o = o0 + c;
                if (O == Opad || o < O) {
                    float v = patch[po * 20 + c];
                    float r;
                    if (MODE == 0)      r = fmaxf(v * __ldg(p0 + o) + __ldg(p1 + o), 0.f);
                    else if (MODE == 1) r = v + __ldg(p0 + o);
                    else                r = v * __ldg(p0 + o) + __ldg(p1 + o);
                    outp[(size_t)(b * O + o) * DHW + pos0 + po] = r;
                }
            }
            __syncwarp();
        }
}

// ================= GroupNorm stats: 2-stage fp32 deterministic =================
__global__ __launch_bounds__(256) void k_gnpart()
{
    __shared__ float rs[256], rs2[256];
    const int grp = blockIdx.x >> 3;     // b*24+gg
    const int slice = blockIdx.x & 7;
    const int tid = threadIdx.x;
    const float4* base = reinterpret_cast<const float4*>(g_w + (size_t)grp * 9 * DHW);
    const int start = slice * 4608;
    float s = 0.f, s2 = 0.f;
#pragma unroll 3
    for (int i = start + tid; i < start + 4608; i += 256) {
        float4 v = base[i];
        s  += (v.x + v.y) + (v.z + v.w);
        s2 += (v.x * v.x + v.y * v.y) + (v.z * v.z + v.w * v.w);
    }
    rs[tid] = s; rs2[tid] = s2; __syncthreads();
    for (int o = 128; o > 0; o >>= 1) {
        if (tid < o) { rs[tid] += rs[tid + o]; rs2[tid] += rs2[tid + o]; }
        __syncthreads();
    }
    if (tid == 0) {
        g_part[blockIdx.x * 2]     = rs[0];
        g_part[blockIdx.x * 2 + 1] = rs2[0];
    }
}
__global__ void k_gnfinal()
{
    const int grp = threadIdx.x;
    if (grp >= 48) return;
    float s = 0.f, s2 = 0.f;
#pragma unroll
    for (int sl = 0; sl < 8; sl++) {
        s  += g_part[(grp * 8 + sl) * 2];
        s2 += g_part[(grp * 8 + sl) * 2 + 1];
    }
    const float n = 9.0f * DHW;
    float mean = s / n;
    float var = s2 / n - mean * mean;
    g_stats[grp * 2] = mean;
    g_stats[grp * 2 + 1] = rsqrtf(var + EPSV);
}

// ================= dynamic 27-tap aggregation + BN4 + swish =================
__global__ __launch_bounds__(128) void k_agg(
    const float* __restrict__ gns, const float* __restrict__ gnb,
    const float* __restrict__ s4, const float* __restrict__ b4)
{
    __shared__ float wn[27 * 4 * 32];   // [tap][y][x]
    __shared__ float vs[12 * 612];      // [c][3z][6y][34x]
    const int bz = blockIdx.z;
    const int b = bz >> 3, gw = bz & 7;
    const int z = blockIdx.y;
    const int y0 = blockIdx.x * 4;
    const int tid = threadIdx.x;
    const int lane = tid & 31, ty = tid >> 5;

    for (int idx = tid; idx < 27 * 128; idx += 128) {
        int tap = idx >> 7; int r = idx & 127;
        int yy = r >> 5, xx = r & 31;
        int ch = gw * 27 + tap;
        int gg = ch / 9;
        float mean = g_stats[(b * 24 + gg) * 2];
        float rstd = g_stats[(b * 24 + gg) * 2 + 1];
        float raw = g_w[(size_t)(b * 216 + ch) * DHW + z * HW + (y0 + yy) * Ww + xx];
        wn[idx] = (raw - mean) * rstd * gns[ch] + gnb[ch];
    }
    __syncthreads();

    float wreg[27];
#pragma unroll
    for (int tap = 0; tap < 27; tap++) wreg[tap] = wn[tap * 128 + ty * 32 + lane];

    for (int cc0 = 0; cc0 < 24; cc0 += 12) {
        __syncthreads();
        for (int idx = tid; idx < 12 * 612; idx += 128) {
            int c = idx / 612; int r = idx - c * 612;
            int zz = r / 204; r -= zz * 204;
            int yy = r / 34; int xx = r - yy * 34;
            int gz = z - 1 + zz, gy = y0 - 1 + yy, gx = xx - 1;
            float v = 0.f;
            if ((unsigned)gz < (unsigned)Dd && (unsigned)gy < (unsigned)Hh &&
                (unsigned)gx < (unsigned)Ww)
                v = g_v[(size_t)(b * DIM + gw * 24 + cc0 + c) * DHW + gz * HW + gy * Ww + gx];
            vs[idx] = v;
        }
        __syncthreads();
        for (int c = 0; c < 12; c++) {
            float a = 0.f;
            const float* vc = vs + c * 612;
#pragma unroll
            for (int dz = 0; dz < 3; dz++)
#pragma unroll
            for (int dy = 0; dy < 3; dy++)
#pragma unroll
            for (int dx = 0; dx < 3; dx++)
                a += wreg[dz * 9 + dy * 3 + dx] *
                     vc[dz * 204 + (ty + dy) * 34 + lane + dx];
            const int ch = gw * 24 + cc0 + c;
            float t = a * s4[ch] + b4[ch];
            float x2v = t / (1.f + expf(-t));
            g_x2[(size_t)(b * DIM + ch) * DHW + z * HW + (y0 + ty) * Ww + lane] = x2v;
        }
    }
}

// ================= global average pool of (x2 + k), float4 =================
__global__ __launch_bounds__(256) void k_gap()
{
    __shared__ float red[256];
    const int row = blockIdx.x;
    const int tid = threadIdx.x;
    const float4* px = reinterpret_cast<const float4*>(g_x2 + (size_t)row * DHW);
    const float4* pk = reinterpret_cast<const float4*>(g_k + (size_t)row * DHW);
    float s = 0.f;
#pragma unroll 4
    for (int i = tid; i < DHW / 4; i += 256) {
        float4 a = px[i]; float4 bq = pk[i];
        s += (a.x + bq.x) + (a.y + bq.y) + (a.z + bq.z) + (a.w + bq.w);
    }
    red[tid] = s; __syncthreads();
    for (int o = 128; o > 0; o >>= 1) {
        if (tid < o) red[tid] += red[tid + o];
        __syncthreads();
    }
    if (tid == 0) g_gap[row] = red[0] * (1.f / DHW);
}

// ================= SE head + softmax attention =================
__global__ __launch_bounds__(192) void k_se(
    const float* __restrict__ w1, const float* __restrict__ bb1,
    const float* __restrict__ bss, const float* __restrict__ bsb,
    const float* __restrict__ w2, const float* __restrict__ bb2)
{
    __shared__ float gap_s[192];
    __shared__ float h1_s[96];
    const int tid = threadIdx.x;
    for (int b = 0; b < Bsz; b++) {
        gap_s[tid] = g_gap[b * DIM + tid];
        __syncthreads();
        if (tid < 96) {
            float a = 0.f;
            for (int i = 0; i < 192; i++) a += w1[tid * 192 + i] * gap_s[i];
            a = (a + bb1[tid]) * bss[tid] + bsb[tid];
            h1_s[tid] = fmaxf(a, 0.f);
        }
        __syncthreads();
        {
            float l0 = bb2[2 * tid], l1 = bb2[2 * tid + 1];
            for (int i = 0; i < 96; i++) {
                float h = h1_s[i];
                l0 += w2[(2 * tid) * 96 + i] * h;
                l1 += w2[(2 * tid + 1) * 96 + i] * h;
            }
            float m = fmaxf(l0, l1);
            float e0 = expf(l0 - m), e1 = expf(l1 - m);
            float inv = 1.f / (e0 + e1);
            g_attn[(b * DIM + tid) * 2] = e0 * inv;
            g_attn[(b * DIM + tid) * 2 + 1] = e1 * inv;
        }
        __syncthreads();
    }
}

// ================= final blend =================
__global__ __launch_bounds__(256) void k_final(float* __restrict__ out)
{
    const int idx = blockIdx.x * 256 + threadIdx.x;
    const int row = idx / (DHW / 4);
    const float a0 = g_attn[row * 2];
    const float a1 = g_attn[row * 2 + 1];
    float4 xv = reinterpret_cast<const float4*>(g_x2)[idx];
    float4 kv = reinterpret_cast<const float4*>(g_k)[idx];
    float4 r;
    r.x = xv.x * a0 + kv.x * a1;
    r.y = xv.y * a0 + kv.y * a1;
    r.z = xv.z * a0 + kv.z * a1;
    r.w = xv.w * a0 + kv.w * a1;
    reinterpret_cast<float4*>(out)[idx] = r;
}

// ================= launch =================
extern "C" void kernel_launch(void* const* d_in, const int* in_sizes, int n_in,
                              void* d_out, int out_size)
{
    const float* x      = (const float*)d_in[0];
    const float* w_key  = (const float*)d_in[1];
    const float* bn1_s  = (const float*)d_in[2];
    const float* bn1_b  = (const float*)d_in[3];
    const float* w_e1   = (const float*)d_in[4];
    const float* bn2_s  = (const float*)d_in[5];
    const float* bn2_b  = (const float*)d_in[6];
    const float* w_e2   = (const float*)d_in[7];
    const float* b_e2   = (const float*)d_in[8];
    const float* gn_s   = (const float*)d_in[9];
    const float* gn_b   = (const float*)d_in[10];
    const float* w_c1   = (const float*)d_in[11];
    const float* bn3_s  = (const float*)d_in[12];
    const float* bn3_b  = (const float*)d_in[13];
    const float* bn4_s  = (const float*)d_in[14];
    const float* bn4_b  = (const float*)d_in[15];
    const float* w_se1  = (const float*)d_in[16];
    const float* b_se1  = (const float*)d_in[17];
    const float* bnse_s = (const float*)d_in[18];
    const float* bnse_b = (const float*)d_in[19];
    const float* w_se2  = (const float*)d_in[20];
    const float* b_se2  = (const float*)d_in[21];
    float* out = (float*)d_out;

    const int conv_smem = (8 * HSTR + 27 * 8 * WSTR) * sizeof(float);  // 81408 B
    cudaFuncSetAttribute(k_conv_mma,
                         cudaFuncAttributeMaxDynamicSharedMemorySize, conv_smem);

    k_prep_gemm<<<(95232 + 255) / 256, 256>>>(w_e1, w_e2, w_c1);              // 0
    k_gemm_mma<192, 192, 192, 2><<<dim3(128, 2), 256>>>(x, bn3_s, bn3_b);     // 1 (v)
    k_prep_conv<<<(248832 + 255) / 256, 256>>>(w_key);                        // 2
    k_conv_mma<<<dim3(4, 16, 8), 256, conv_smem>>>(x, bn1_s, bn1_b);          // 3 (captured)
    k_gemm_mma<96, 96, 384, 0><<<dim3(128, 2), 256>>>(x, bn2_s, bn2_b);       // 4 (e)
    k_gemm_mma<216, 224, 96, 1><<<dim3(128, 2), 256>>>(x, b_e2, b_e2);        // 5 (w)
    k_gnpart<<<48 * 8, 256>>>();
    k_gnfinal<<<1, 64>>>();
    k_agg<<<dim3(8, 16, 16), 128>>>(gn_s, gn_b, bn4_s, bn4_b);
    k_gap<<<Bsz * DIM, 256>>>();
    k_se<<<1, 192>>>(w_se1, b_se1, bnse_s, bnse_b, w_se2, b_se2);
    k_final<<<(Bsz * DIM * DHW / 4) / 256, 256>>>(out);
}

// round 11
// speedup vs baseline: 1.0029x; 1.0029x over previous
#include <cuda_runtime.h>
#include <math.h>
#include <cstdint>
#include <mma.h>

using namespace nvcuda;

#define Bsz 2
#define DIM 192
#define Dd 16
#define Hh 32
#define Ww 32
#define HW 1024
#define DHW 16384
#define EPSV 1e-5f

// ---------------- scratch (device globals; no allocations allowed) ----------------
__device__ float g_k  [Bsz * DIM * DHW];     // key conv output (post BN+ReLU)
__device__ float g_e  [Bsz * 96  * DHW];     // embed 1
__device__ float g_w  [Bsz * 216 * DHW];     // dyn weights pre-GN (biased)
__device__ float g_v  [Bsz * DIM * DHW];     // value conv output
__device__ float g_x2 [Bsz * DIM * DHW];     // aggregated + swish
__device__ float g_stats[Bsz * 24 * 2];      // per (b, gn-group): mean, rstd
__device__ float g_part [Bsz * 24 * 8 * 2];  // partial sums (deterministic 2-stage)
__device__ float g_gap[Bsz * DIM];
__device__ float g_attn[Bsz * DIM * 2];
// pre-transposed tf32 weights (accessed ONLY from device code!)
__device__ float g_wconv[4 * 27 * 48 * 48];  // [g][tap][ci][co]
__device__ float g_we1t[384 * 96];           // [i][o]
__device__ float g_we2t[96 * 224];           // [i][o] (216 padded to 224 w/ zeros)
__device__ float g_wc1t[192 * 192];          // [i][o]

// ================= helpers =================
__device__ __forceinline__ float f2tf(float f) {
    uint32_t u;
    asm("cvt.rna.tf32.f32 %0, %1;" : "=r"(u) : "f"(f));
    return __uint_as_float(u);
}

// ================= prep kernels: transpose + tf32-convert weights =================
__global__ __launch_bounds__(256) void k_prep_gemm(
    const float* __restrict__ w_e1, const float* __restrict__ w_e2,
    const float* __restrict__ w_c1)
{
    int id = blockIdx.x * 256 + threadIdx.x;
    if (id < 36864) {
        int i = id / 96, o = id % 96;
        g_we1t[id] = f2tf(w_e1[o * 384 + i]);
    } else if (id < 36864 + 21504) {
        int r = id - 36864;
        int i = r / 224, o = r % 224;
        g_we2t[r] = (o < 216) ? f2tf(w_e2[o * 96 + i]) : 0.f;
    } else if (id < 36864 + 21504 + 36864) {
        int r = id - 36864 - 21504;
        int i = r / 192, o = r % 192;
        g_wc1t[r] = f2tf(w_c1[o * 192 + i]);
    }
}
__global__ __launch_bounds__(256) void k_prep_conv(const float* __restrict__ w_key)
{
    int id = blockIdx.x * 256 + threadIdx.x;
    if (id < 248832) {
        int co = id % 48;
        int ci = (id / 48) % 48;
        int tap = (id / 2304) % 27;
        int g = id / 62208;
        g_wconv[id] = f2tf(w_key[((size_t)(g * 48 + co) * 48 + ci) * 27 + tap]);
    }
}

// ================= conv 3x3x3 grouped, implicit GEMM via wmma tf32 =================
// block: 256 thr = 8 warps; tile 256 pos (8y x 32x at one z) x 48 co.
// warp w owns m-tiles {2w, 2w+1} (16 pos each) x all 3 n-tiles of 16 co.
// v2: all-27-tap weight staging (2 syncs/ci-chunk), strength-reduced halo
//     staging, dynamic smem 81.4 KB.
#define HSTR 1032   // halo ci-stride in floats (mod 32 == 8)
#define WSTR 56     // weight ci-stride (mod 32 == 24)
__global__ __launch_bounds__(256, 2) void k_conv_mma(
    const float* __restrict__ x, const float* __restrict__ s1,
    const float* __restrict__ b1)
{
    extern __shared__ float smem[];        // 8*HSTR + 27*8*WSTR floats
    float* hs = smem;                      // 8256 floats
    float* ws = smem + 8 * HSTR;           // 12096 floats

    const int tid = threadIdx.x;
    const int lane = tid & 31, warp = tid >> 5;
    const int bz = blockIdx.z;
    const int b = bz >> 2, g = bz & 3;
    const int z = blockIdx.y;
    const int y0 = blockIdx.x * 8;

    wmma::fragment<wmma::accumulator, 16, 16, 8, float> acc[2][3];
#pragma unroll
    for (int mt = 0; mt < 2; mt++)
#pragma unroll
        for (int j = 0; j < 3; j++) wmma::fill_fragment(acc[mt][j], 0.f);

    const float* xg = x + (size_t)(b * DIM + g * 48) * DHW;
    const float* wg = g_wconv + (size_t)g * 27 * 48 * 48;

    for (int ci0 = 0; ci0 < 48; ci0 += 8) {
        __syncthreads();
        // ---- stage halo: 240 rows (8ci x 3zz x 10yy) of 34 cols; warp = row ----
        for (int R = warp; R < 240; R += 8) {
            int ci = R / 30;
            int r2 = R - ci * 30;
            int zz = r2 / 10, yy = r2 - zz * 10;
            int gz = z - 1 + zz, gy = y0 - 1 + yy;
            bool rowok = ((unsigned)gz < (unsigned)Dd) & ((unsigned)gy < (unsigned)Hh);
            const float* src = xg + (size_t)(ci0 + ci) * DHW + gz * HW + gy * Ww;
            float* dst = hs + ci * HSTR + zz * 340 + yy * 34;
            int gx = lane - 1;
            float v = (rowok && (unsigned)gx < (unsigned)Ww) ? src[gx] : 0.f;
            dst[lane] = f2tf(v);
            if (lane < 2) {
                int gx2 = 31 + lane;
                float v2 = (rowok && (unsigned)gx2 < (unsigned)Ww) ? src[gx2] : 0.f;
                dst[32 + lane] = f2tf(v2);
            }
        }
        // ---- stage ALL 27 taps of weights for this ci-chunk: [tap][ci][co] ----
        for (int idx = tid; idx < 27 * 8 * 48; idx += 256) {
            int t = idx / 384; int r = idx - t * 384;
            int ci = r / 48, co = r - ci * 48;
            ws[t * (8 * WSTR) + ci * WSTR + co] =
                wg[((size_t)t * 48 + ci0 + ci) * 48 + co];
        }
        __syncthreads();

        for (int dz = 0; dz < 3; dz++) {
            const float* hz = hs + dz * 340;
            const float* wz = ws + dz * 9 * (8 * WSTR);
#pragma unroll
            for (int t9 = 0; t9 < 9; t9++) {
                const int dy = t9 / 3, dx = t9 % 3;
                wmma::fragment<wmma::matrix_b, 16, 16, 8,
                               wmma::precision::tf32, wmma::row_major> bf[3];
#pragma unroll
                for (int j = 0; j < 3; j++)
                    wmma::load_matrix_sync(bf[j], wz + t9 * (8 * WSTR) + j * 16, WSTR);
#pragma unroll
                for (int mt = 0; mt < 2; mt++) {
                    const int mtile = warp * 2 + mt;
                    const int yy = mtile >> 1, xx0 = (mtile & 1) * 16;
                    const float* aptr = hz + (yy + dy) * 34 + xx0 + dx;
                    wmma::fragment<wmma::matrix_a, 16, 16, 8,
                                   wmma::precision::tf32, wmma::col_major> af;
                    wmma::load_matrix_sync(af, aptr, HSTR);
#pragma unroll
                    for (int j = 0; j < 3; j++)
                        wmma::mma_sync(acc[mt][j], af, bf[j], acc[mt][j]);
                }
            }
        }
    }

    // ---- epilogue: stage full 256x48 tile in smem (reuse), BN+ReLU store ----
    __syncthreads();
#pragma unroll
    for (int mt = 0; mt < 2; mt++)
#pragma unroll
        for (int j = 0; j < 3; j++)
            wmma::store_matrix_sync(smem + (warp * 32 + mt * 16) * 48 + j * 16,
                                    acc[mt][j], 48, wmma::mem_row_major);
    __syncthreads();
    for (int i = tid; i < 12288; i += 256) {
        int ch = i >> 8, pos = i & 255;
        int chg = g * 48 + ch;
        float v = smem[pos * 48 + ch] * __ldg(s1 + chg) + __ldg(b1 + chg);
        g_k[(size_t)(b * DIM + chg) * DHW + z * HW + y0 * Ww + pos] = fmaxf(v, 0.f);
    }
}

// ================= 1x1 conv GEMM via wmma tf32 =================
// D[128 pos, Opad] = A[pos, I] x Wt[I, Opad].  channel-major in/out.
// MODE 0: e = relu(bn2(.)) from concat(x, g_k), O=96,  I=384 -> g_e
// MODE 1: w = . + b_e2 from g_e,                O=216, I=96  -> g_w
// MODE 2: v = bn3(.) from x,                    O=192, I=192 -> g_v
template <int O, int Opad, int I, int MODE>
__global__ __launch_bounds__(256) void k_gemm_mma(
    const float* __restrict__ x,
    const float* __restrict__ p0, const float* __restrict__ p1)
{
    constexpr int ASTR = 136;
    constexpr int BSTR = Opad + 8;
    constexpr int NT = Opad / 32;       // n-tiles per warp
    __shared__ float As[32 * ASTR];     // also reused as epilogue patches
    __shared__ float Bs[32 * BSTR];

    const float* __restrict__ Wt =
        (MODE == 0) ? g_we1t : (MODE == 1) ? g_we2t : g_wc1t;

    const int tid = threadIdx.x;
    const int lane = tid & 31, warp = tid >> 5;
    const int mw = warp & 3, nw = warp >> 2;
    const int b = blockIdx.y;
    const int pbase = blockIdx.x * 128;

    wmma::fragment<wmma::accumulator, 16, 16, 8, float> acc[2][NT];
#pragma unroll
    for (int mt = 0; mt < 2; mt++)
#pragma unroll
        for (int j = 0; j < NT; j++) wmma::fill_fragment(acc[mt][j], 0.f);

    for (int i0 = 0; i0 < I; i0 += 32) {
        // stage A: 32 k x 128 pos (tf32)
#pragma unroll
        for (int r = 0; r < 4; r++) {
            int idx = tid + r * 256;
            int k = idx >> 5, p4 = idx & 31;
            int ch = i0 + k;
            const float* srow;
            if (MODE == 0)
                srow = (ch < DIM) ? x + (size_t)(b * DIM + ch) * DHW
                                  : g_k + (size_t)(b * DIM + ch - DIM) * DHW;
            else if (MODE == 1)
                srow = g_e + (size_t)(b * 96 + ch) * DHW;
            else
                srow = x + (size_t)(b * DIM + ch) * DHW;
            float4 v = *reinterpret_cast<const float4*>(srow + pbase + p4 * 4);
            float* dst = As + k * ASTR + p4 * 4;
            dst[0] = f2tf(v.x); dst[1] = f2tf(v.y);
            dst[2] = f2tf(v.z); dst[3] = f2tf(v.w);
        }
        // stage B: 32 k x Opad (already tf32)
        for (int idx = tid; idx < 32 * (Opad / 4); idx += 256) {
            int k = idx / (Opad / 4), q4 = idx - k * (Opad / 4);
            float4 wv = *reinterpret_cast<const float4*>(
                Wt + (size_t)(i0 + k) * Opad + q4 * 4);
            float* dst = Bs + k * BSTR + q4 * 4;
            dst[0] = wv.x; dst[1] = wv.y; dst[2] = wv.z; dst[3] = wv.w;
        }
        __syncthreads();
#pragma unroll
        for (int ks = 0; ks < 4; ks++) {
            wmma::fragment<wmma::matrix_a, 16, 16, 8,
                           wmma::precision::tf32, wmma::col_major> af[2];
#pragma unroll
            for (int mt = 0; mt < 2; mt++)
                wmma::load_matrix_sync(af[mt],
                    As + ks * 8 * ASTR + mw * 32 + mt * 16, ASTR);
#pragma unroll
            for (int j = 0; j < NT; j++) {
                wmma::fragment<wmma::matrix_b, 16, 16, 8,
                               wmma::precision::tf32, wmma::row_major> bf;
                wmma::load_matrix_sync(bf,
                    Bs + ks * 8 * BSTR + (nw * NT + j) * 16, BSTR);
                wmma::mma_sync(acc[0][j], af[0], bf, acc[0][j]);
                wmma::mma_sync(acc[1][j], af[1], bf, acc[1][j]);
            }
        }
        __syncthreads();
    }

    // ---- epilogue via per-warp smem patch (reuse As) ----
    float* patch = As + warp * 320;     // 16 x 20
    float* outp = (MODE == 0) ? g_e : (MODE == 1) ? g_w : g_v;
#pragma unroll
    for (int mt = 0; mt < 2; mt++)
#pragma unroll
        for (int j = 0; j < NT; j++) {
            wmma::store_matrix_sync(patch, acc[mt][j], 20, wmma::mem_row_major);
            __syncwarp();
            int pos0 = pbase + mw * 32 + mt * 16;
            int o0 = (nw * NT + j) * 16;
            int po = lane & 15, half = lane >> 4;
#pragma unroll
            for (int p = 0; p < 8; p++) {
                int c = p * 2 + half;
                int o = o0 + c;
                if (O == Opad || o < O) {
                    float v = patch[po * 20 + c];
                    float r;
                    if (MODE == 0)      r = fmaxf(v * __ldg(p0 + o) + __ldg(p1 + o), 0.f);
                    else if (MODE == 1) r = v + __ldg(p0 + o);
                    else                r = v * __ldg(p0 + o) + __ldg(p1 + o);
                    outp[(size_t)(b * O + o) * DHW + pos0 + po] = r;
                }
            }
            __syncwarp();
        }
}

// ================= GroupNorm stats: 2-stage fp32 deterministic =================
__global__ __launch_bounds__(256) void k_gnpart()
{
    __shared__ float rs[256], rs2[256];
    const int grp = blockIdx.x >> 3;     // b*24+gg
    const int slice = blockIdx.x & 7;
    const int tid = threadIdx.x;
    const float4* base = reinterpret_cast<const float4*>(g_w + (size_t)grp * 9 * DHW);
    const int start = slice * 4608;
    float s = 0.f, s2 = 0.f;
#pragma unroll 3
    for (int i = start + tid; i < start + 4608; i += 256) {
        float4 v = base[i];
        s  += (v.x + v.y) + (v.z + v.w);
        s2 += (v.x * v.x + v.y * v.y) + (v.z * v.z + v.w * v.w);
    }
    rs[tid] = s; rs2[tid] = s2; __syncthreads();
    for (int o = 128; o > 0; o >>= 1) {
        if (tid < o) { rs[tid] += rs[tid + o]; rs2[tid] += rs2[tid + o]; }
        __syncthreads();
    }
    if (tid == 0) {
        g_part[blockIdx.x * 2]     = rs[0];
        g_part[blockIdx.x * 2 + 1] = rs2[0];
    }
}
__global__ void k_gnfinal()
{
    const int grp = threadIdx.x;
    if (grp >= 48) return;
    float s = 0.f, s2 = 0.f;
#pragma unroll
    for (int sl = 0; sl < 8; sl++) {
        s  += g_part[(grp * 8 + sl) * 2];
        s2 += g_part[(grp * 8 + sl) * 2 + 1];
    }
    const float n = 9.0f * DHW;
    float mean = s / n;
    float var = s2 / n - mean * mean;
    g_stats[grp * 2] = mean;
    g_stats[grp * 2 + 1] = rsqrtf(var + EPSV);
}

// ================= dynamic 27-tap aggregation + BN4 + swish =================
__global__ __launch_bounds__(128) void k_agg(
    const float* __restrict__ gns, const float* __restrict__ gnb,
    const float* __restrict__ s4, const float* __restrict__ b4)
{
    __shared__ float wn[27 * 4 * 32];   // [tap][y][x]
    __shared__ float vs[12 * 612];      // [c][3z][6y][34x]
    const int bz = blockIdx.z;
    const int b = bz >> 3, gw = bz & 7;
    const int z = blockIdx.y;
    const int y0 = blockIdx.x * 4;
    const int tid = threadIdx.x;
    const int lane = tid & 31, ty = tid >> 5;

    for (int idx = tid; idx < 27 * 128; idx += 128) {
        int tap = idx >> 7; int r = idx & 127;
        int yy = r >> 5, xx = r & 31;
        int ch = gw * 27 + tap;
        int gg = ch / 9;
        float mean = g_stats[(b * 24 + gg) * 2];
        float rstd = g_stats[(b * 24 + gg) * 2 + 1];
        float raw = g_w[(size_t)(b * 216 + ch) * DHW + z * HW + (y0 + yy) * Ww + xx];
        wn[idx] = (raw - mean) * rstd * gns[ch] + gnb[ch];
    }
    __syncthreads();

    float wreg[27];
#pragma unroll
    for (int tap = 0; tap < 27; tap++) wreg[tap] = wn[tap * 128 + ty * 32 + lane];

    for (int cc0 = 0; cc0 < 24; cc0 += 12) {
        __syncthreads();
        for (int idx = tid; idx < 12 * 612; idx += 128) {
            int c = idx / 612; int r = idx - c * 612;
            int zz = r / 204; r -= zz * 204;
            int yy = r / 34; int xx = r - yy * 34;
            int gz = z - 1 + zz, gy = y0 - 1 + yy, gx = xx - 1;
            float v = 0.f;
            if ((unsigned)gz < (unsigned)Dd && (unsigned)gy < (unsigned)Hh &&
                (unsigned)gx < (unsigned)Ww)
                v = g_v[(size_t)(b * DIM + gw * 24 + cc0 + c) * DHW + gz * HW + gy * Ww + gx];
            vs[idx] = v;
        }
        __syncthreads();
        for (int c = 0; c < 12; c++) {
            float a = 0.f;
            const float* vc = vs + c * 612;
#pragma unroll
            for (int dz = 0; dz < 3; dz++)
#pragma unroll
            for (int dy = 0; dy < 3; dy++)
#pragma unroll
            for (int dx = 0; dx < 3; dx++)
                a += wreg[dz * 9 + dy * 3 + dx] *
                     vc[dz * 204 + (ty + dy) * 34 + lane + dx];
            const int ch = gw * 24 + cc0 + c;
            float t = a * s4[ch] + b4[ch];
            float x2v = t / (1.f + expf(-t));
            g_x2[(size_t)(b * DIM + ch) * DHW + z * HW + (y0 + ty) * Ww + lane] = x2v;
        }
    }
}

// ================= global average pool of (x2 + k), float4 =================
__global__ __launch_bounds__(256) void k_gap()
{
    __shared__ float red[256];
    const int row = blockIdx.x;
    const int tid = threadIdx.x;
    const float4* px = reinterpret_cast<const float4*>(g_x2 + (size_t)row * DHW);
    const float4* pk = reinterpret_cast<const float4*>(g_k + (size_t)row * DHW);
    float s = 0.f;
#pragma unroll 4
    for (int i = tid; i < DHW / 4; i += 256) {
        float4 a = px[i]; float4 bq = pk[i];
        s += (a.x + bq.x) + (a.y + bq.y) + (a.z + bq.z) + (a.w + bq.w);
    }
    red[tid] = s; __syncthreads();
    for (int o = 128; o > 0; o >>= 1) {
        if (tid < o) red[tid] += red[tid + o];
        __syncthreads();
    }
    if (tid == 0) g_gap[row] = red[0] * (1.f / DHW);
}

// ================= SE head + softmax attention =================
__global__ __launch_bounds__(192) void k_se(
    const float* __restrict__ w1, const float* __restrict__ bb1,
    const float* __restrict__ bss, const float* __restrict__ bsb,
    const float* __restrict__ w2, const float* __restrict__ bb2)
{
    __shared__ float gap_s[192];
    __shared__ float h1_s[96];
    const int tid = threadIdx.x;
    for (int b = 0; b < Bsz; b++) {
        gap_s[tid] = g_gap[b * DIM + tid];
        __syncthreads();
        if (tid < 96) {
            float a = 0.f;
            for (int i = 0; i < 192; i++) a += w1[tid * 192 + i] * gap_s[i];
            a = (a + bb1[tid]) * bss[tid] + bsb[tid];
            h1_s[tid] = fmaxf(a, 0.f);
        }
        __syncthreads();
        {
            float l0 = bb2[2 * tid], l1 = bb2[2 * tid + 1];
            for (int i = 0; i < 96; i++) {
                float h = h1_s[i];
                l0 += w2[(2 * tid) * 96 + i] * h;
                l1 += w2[(2 * tid + 1) * 96 + i] * h;
            }
            float m = fmaxf(l0, l1);
            float e0 = expf(l0 - m), e1 = expf(l1 - m);
            float inv = 1.f / (e0 + e1);
            g_attn[(b * DIM + tid) * 2] = e0 * inv;
            g_attn[(b * DIM + tid) * 2 + 1] = e1 * inv;
        }
        __syncthreads();
    }
}

// ================= final blend =================
__global__ __launch_bounds__(256) void k_final(float* __restrict__ out)
{
    const int idx = blockIdx.x * 256 + threadIdx.x;
    const int row = idx / (DHW / 4);
    const float a0 = g_attn[row * 2];
    const float a1 = g_attn[row * 2 + 1];
    float4 xv = reinterpret_cast<const float4*>(g_x2)[idx];
    float4 kv = reinterpret_cast<const float4*>(g_k)[idx];
    float4 r;
    r.x = xv.x * a0 + kv.x * a1;
    r.y = xv.y * a0 + kv.y * a1;
    r.z = xv.z * a0 + kv.z * a1;
    r.w = xv.w * a0 + kv.w * a1;
    reinterpret_cast<float4*>(out)[idx] = r;
}

// ================= launch =================
extern "C" void kernel_launch(void* const* d_in, const int* in_sizes, int n_in,
                              void* d_out, int out_size)
{
    const float* x      = (const float*)d_in[0];
    const float* w_key  = (const float*)d_in[1];
    const float* bn1_s  = (const float*)d_in[2];
    const float* bn1_b  = (const float*)d_in[3];
    const float* w_e1   = (const float*)d_in[4];
    const float* bn2_s  = (const float*)d_in[5];
    const float* bn2_b  = (const float*)d_in[6];
    const float* w_e2   = (const float*)d_in[7];
    const float* b_e2   = (const float*)d_in[8];
    const float* gn_s   = (const float*)d_in[9];
    const float* gn_b   = (const float*)d_in[10];
    const float* w_c1   = (const float*)d_in[11];
    const float* bn3_s  = (const float*)d_in[12];
    const float* bn3_b  = (const float*)d_in[13];
    const float* bn4_s  = (const float*)d_in[14];
    const float* bn4_b  = (const float*)d_in[15];
    const float* w_se1  = (const float*)d_in[16];
    const float* b_se1  = (const float*)d_in[17];
    const float* bnse_s = (const float*)d_in[18];
    const float* bnse_b = (const float*)d_in[19];
    const float* w_se2  = (const float*)d_in[20];
    const float* b_se2  = (const float*)d_in[21];
    float* out = (float*)d_out;

    const int conv_smem = (8 * HSTR + 27 * 8 * WSTR) * sizeof(float);  // 81408 B
    cudaFuncSetAttribute(k_conv_mma,
                         cudaFuncAttributeMaxDynamicSharedMemorySize, conv_smem);

    k_prep_gemm<<<(95232 + 255) / 256, 256>>>(w_e1, w_e2, w_c1);              // 0
    k_gemm_mma<192, 192, 192, 2><<<dim3(128, 2), 256>>>(x, bn3_s, bn3_b);     // 1 (v)
    k_prep_conv<<<(248832 + 255) / 256, 256>>>(w_key);                        // 2
    k_conv_mma<<<dim3(4, 16, 8), 256, conv_smem>>>(x, bn1_s, bn1_b);          // 3 (captured)
    k_gemm_mma<96, 96, 384, 0><<<dim3(128, 2), 256>>>(x, bn2_s, bn2_b);       // 4 (e)
    k_gemm_mma<216, 224, 96, 1><<<dim3(128, 2), 256>>>(x, b_e2, b_e2);        // 5 (w)
    k_gnpart<<<48 * 8, 256>>>();
    k_gnfinal<<<1, 64>>>();
    k_agg<<<dim3(8, 16, 16), 128>>>(gn_s, gn_b, bn4_s, bn4_b);
    k_gap<<<Bsz * DIM, 256>>>();
    k_se<<<1, 192>>>(w_se1, b_se1, bnse_s, bnse_b, w_se2, b_se2);
    k_final<<<(Bsz * DIM * DHW / 4) / 256, 256>>>(out);
}

// round 12
// speedup vs baseline: 1.0567x; 1.0536x over previous
#include <cuda_runtime.h>
#include <math.h>
#include <cstdint>
#include <mma.h>

using namespace nvcuda;

#define Bsz 2
#define DIM 192
#define Dd 16
#define Hh 32
#define Ww 32
#define HW 1024
#define DHW 16384
#define EPSV 1e-5f

// ---------------- scratch (device globals; no allocations allowed) ----------------
__device__ float g_k  [Bsz * DIM * DHW];     // key conv output (post BN+ReLU)
__device__ float g_e  [Bsz * 96  * DHW];     // embed 1
__device__ float g_w  [Bsz * 216 * DHW];     // dyn weights pre-GN (biased)
__device__ float g_v  [Bsz * DIM * DHW];     // value conv output
__device__ float g_x2 [Bsz * DIM * DHW];     // aggregated + swish
__device__ float g_stats[Bsz * 24 * 2];      // per (b, gn-group): mean, rstd
__device__ float g_part [Bsz * 24 * 8 * 2];  // partial sums (deterministic 2-stage)
__device__ float g_gap[Bsz * DIM];
__device__ float g_attn[Bsz * DIM * 2];
// pre-transposed tf32 weights (accessed ONLY from device code!)
__device__ float g_wconv[4 * 27 * 48 * 48];  // [g][tap][ci][co]
__device__ float g_we1t[384 * 96];           // [i][o]
__device__ float g_we2t[96 * 224];           // [i][o] (216 padded to 224 w/ zeros)
__device__ float g_wc1t[192 * 192];          // [i][o]

// ================= helpers =================
__device__ __forceinline__ float f2tf(float f) {
    uint32_t u;
    asm("cvt.rna.tf32.f32 %0, %1;" : "=r"(u) : "f"(f));
    return __uint_as_float(u);
}

// ================= prep kernels: transpose + tf32-convert weights =================
__global__ __launch_bounds__(256) void k_prep_gemm(
    const float* __restrict__ w_e1, const float* __restrict__ w_e2,
    const float* __restrict__ w_c1)
{
    int id = blockIdx.x * 256 + threadIdx.x;
    if (id < 36864) {
        int i = id / 96, o = id % 96;
        g_we1t[id] = f2tf(w_e1[o * 384 + i]);
    } else if (id < 36864 + 21504) {
        int r = id - 36864;
        int i = r / 224, o = r % 224;
        g_we2t[r] = (o < 216) ? f2tf(w_e2[o * 96 + i]) : 0.f;
    } else if (id < 36864 + 21504 + 36864) {
        int r = id - 36864 - 21504;
        int i = r / 192, o = r % 192;
        g_wc1t[r] = f2tf(w_c1[o * 192 + i]);
    }
}
__global__ __launch_bounds__(256) void k_prep_conv(const float* __restrict__ w_key)
{
    int id = blockIdx.x * 256 + threadIdx.x;
    if (id < 248832) {
        int co = id % 48;
        int ci = (id / 48) % 48;
        int tap = (id / 2304) % 27;
        int g = id / 62208;
        g_wconv[id] = f2tf(w_key[((size_t)(g * 48 + co) * 48 + ci) * 27 + tap]);
    }
}

// ================= conv 3x3x3 grouped, implicit GEMM via wmma tf32 =================
// (round-8 known-good version: static 48KB smem union, per-dz weight staging)
#define HSTR 1032   // halo ci-stride in floats
#define WSTR 56     // weight ci-stride
__global__ __launch_bounds__(256) void k_conv_mma(
    const float* __restrict__ x, const float* __restrict__ s1,
    const float* __restrict__ b1)
{
    __shared__ float smem[12288];          // 48 KB union
    float* hs = smem;                      // 8 * HSTR = 8256 floats
    float* ws = smem + 8 * HSTR;           // 9 * 8 * WSTR = 4032 floats

    const int tid = threadIdx.x;
    const int warp = tid >> 5;
    const int bz = blockIdx.z;
    const int b = bz >> 2, g = bz & 3;
    const int z = blockIdx.y;
    const int y0 = blockIdx.x * 8;

    wmma::fragment<wmma::accumulator, 16, 16, 8, float> acc[2][3];
#pragma unroll
    for (int mt = 0; mt < 2; mt++)
#pragma unroll
        for (int j = 0; j < 3; j++) wmma::fill_fragment(acc[mt][j], 0.f);

    const float* xg = x + (size_t)(b * DIM + g * 48) * DHW;
    const float* wg = g_wconv + (size_t)g * 27 * 48 * 48;

    for (int ci0 = 0; ci0 < 48; ci0 += 8) {
        __syncthreads();
        // stage halo: 8 ci x (3z x 10y x 34x), tf32-rounded
        for (int idx = tid; idx < 8160; idx += 256) {
            int ci = idx / 1020, r = idx - ci * 1020;
            int zz = r / 340; r -= zz * 340;
            int yy = r / 34;  int xx = r - yy * 34;
            int gz = z - 1 + zz, gy = y0 - 1 + yy, gx = xx - 1;
            float v = 0.f;
            if ((unsigned)gz < (unsigned)Dd && (unsigned)gy < (unsigned)Hh &&
                (unsigned)gx < (unsigned)Ww)
                v = xg[(size_t)(ci0 + ci) * DHW + gz * HW + gy * Ww + gx];
            hs[ci * HSTR + zz * 340 + yy * 34 + xx] = f2tf(v);
        }
        for (int dz = 0; dz < 3; dz++) {
            __syncthreads();
            // stage weights for the 9 taps of this dz: [t9][ci][co]
            for (int idx = tid; idx < 9 * 8 * 48; idx += 256) {
                int t9 = idx / 384, r = idx - t9 * 384;
                int ci = r / 48, co = r - ci * 48;
                ws[t9 * (8 * WSTR) + ci * WSTR + co] =
                    wg[((size_t)(dz * 9 + t9) * 48 + ci0 + ci) * 48 + co];
            }
            __syncthreads();
#pragma unroll
            for (int t9 = 0; t9 < 9; t9++) {
                const int dy = t9 / 3, dx = t9 % 3;
                wmma::fragment<wmma::matrix_b, 16, 16, 8,
                               wmma::precision::tf32, wmma::row_major> bf[3];
#pragma unroll
                for (int j = 0; j < 3; j++)
                    wmma::load_matrix_sync(bf[j], ws + t9 * (8 * WSTR) + j * 16, WSTR);
#pragma unroll
                for (int mt = 0; mt < 2; mt++) {
                    const int mtile = warp * 2 + mt;
                    const int yy = mtile >> 1, xx0 = (mtile & 1) * 16;
                    const float* aptr = hs + dz * 340 + (yy + dy) * 34 + xx0 + dx;
                    wmma::fragment<wmma::matrix_a, 16, 16, 8,
                                   wmma::precision::tf32, wmma::col_major> af;
                    wmma::load_matrix_sync(af, aptr, HSTR);
#pragma unroll
                    for (int j = 0; j < 3; j++)
                        wmma::mma_sync(acc[mt][j], af, bf[j], acc[mt][j]);
                }
            }
        }
    }

    // ---- epilogue: stage full 256x48 tile in smem (union), then BN+ReLU store ----
    __syncthreads();
#pragma unroll
    for (int mt = 0; mt < 2; mt++)
#pragma unroll
        for (int j = 0; j < 3; j++)
            wmma::store_matrix_sync(smem + (warp * 32 + mt * 16) * 48 + j * 16,
                                    acc[mt][j], 48, wmma::mem_row_major);
    __syncthreads();
    for (int i = tid; i < 12288; i += 256) {
        int ch = i >> 8, pos = i & 255;
        int chg = g * 48 + ch;
        float v = smem[pos * 48 + ch] * __ldg(s1 + chg) + __ldg(b1 + chg);
        g_k[(size_t)(b * DIM + chg) * DHW + z * HW + y0 * Ww + pos] = fmaxf(v, 0.f);
    }
}

// ================= 1x1 conv GEMM via wmma tf32 =================
// D[128 pos, Opad] = A[pos, I] x Wt[I, Opad].  channel-major in/out.
// MODE 0: e = relu(bn2(.)) from concat(x, g_k), O=96,  I=384 -> g_e
// MODE 1: w = . + b_e2 from g_e,                O=216, I=96  -> g_w
// MODE 2: v = bn3(.) from x,                    O=192, I=192 -> g_v
template <int O, int Opad, int I, int MODE>
__global__ __launch_bounds__(256) void k_gemm_mma(
    const float* __restrict__ x,
    const float* __restrict__ p0, const float* __restrict__ p1)
{
    constexpr int ASTR = 136;
    constexpr int BSTR = Opad + 8;
    constexpr int NT = Opad / 32;       // n-tiles per warp
    __shared__ float As[32 * ASTR];     // also reused as epilogue patches
    __shared__ float Bs[32 * BSTR];

    const float* __restrict__ Wt =
        (MODE == 0) ? g_we1t : (MODE == 1) ? g_we2t : g_wc1t;

    const int tid = threadIdx.x;
    const int lane = tid & 31, warp = tid >> 5;
    const int mw = warp & 3, nw = warp >> 2;
    const int b = blockIdx.y;
    const int pbase = blockIdx.x * 128;

    wmma::fragment<wmma::accumulator, 16, 16, 8, float> acc[2][NT];
#pragma unroll
    for (int mt = 0; mt < 2; mt++)
#pragma unroll
        for (int j = 0; j < NT; j++) wmma::fill_fragment(acc[mt][j], 0.f);

    for (int i0 = 0; i0 < I; i0 += 32) {
        // stage A: 32 k x 128 pos (tf32)
#pragma unroll
        for (int r = 0; r < 4; r++) {
            int idx = tid + r * 256;
            int k = idx >> 5, p4 = idx & 31;
            int ch = i0 + k;
            const float* srow;
            if (MODE == 0)
                srow = (ch < DIM) ? x + (size_t)(b * DIM + ch) * DHW
                                  : g_k + (size_t)(b * DIM + ch - DIM) * DHW;
            else if (MODE == 1)
                srow = g_e + (size_t)(b * 96 + ch) * DHW;
            else
                srow = x + (size_t)(b * DIM + ch) * DHW;
            float4 v = *reinterpret_cast<const float4*>(srow + pbase + p4 * 4);
            float* dst = As + k * ASTR + p4 * 4;
            dst[0] = f2tf(v.x); dst[1] = f2tf(v.y);
            dst[2] = f2tf(v.z); dst[3] = f2tf(v.w);
        }
        // stage B: 32 k x Opad (already tf32)
        for (int idx = tid; idx < 32 * (Opad / 4); idx += 256) {
            int k = idx / (Opad / 4), q4 = idx - k * (Opad / 4);
            float4 wv = *reinterpret_cast<const float4*>(
                Wt + (size_t)(i0 + k) * Opad + q4 * 4);
            float* dst = Bs + k * BSTR + q4 * 4;
            dst[0] = wv.x; dst[1] = wv.y; dst[2] = wv.z; dst[3] = wv.w;
        }
        __syncthreads();
#pragma unroll
        for (int ks = 0; ks < 4; ks++) {
            wmma::fragment<wmma::matrix_a, 16, 16, 8,
                           wmma::precision::tf32, wmma::col_major> af[2];
#pragma unroll
            for (int mt = 0; mt < 2; mt++)
                wmma::load_matrix_sync(af[mt],
                    As + ks * 8 * ASTR + mw * 32 + mt * 16, ASTR);
#pragma unroll
            for (int j = 0; j < NT; j++) {
                wmma::fragment<wmma::matrix_b, 16, 16, 8,
                               wmma::precision::tf32, wmma::row_major> bf;
                wmma::load_matrix_sync(bf,
                    Bs + ks * 8 * BSTR + (nw * NT + j) * 16, BSTR);
                wmma::mma_sync(acc[0][j], af[0], bf, acc[0][j]);
                wmma::mma_sync(acc[1][j], af[1], bf, acc[1][j]);
            }
        }
        __syncthreads();
    }

    // ---- epilogue via per-warp smem patch (reuse As) ----
    float* patch = As + warp * 320;     // 16 x 20
    float* outp = (MODE == 0) ? g_e : (MODE == 1) ? g_w : g_v;
#pragma unroll
    for (int mt = 0; mt < 2; mt++)
#pragma unroll
        for (int j = 0; j < NT; j++) {
            wmma::store_matrix_sync(patch, acc[mt][j], 20, wmma::mem_row_major);
            __syncwarp();
            int pos0 = pbase + mw * 32 + mt * 16;
            int o0 = (nw * NT + j) * 16;
            int po = lane & 15, half = lane >> 4;
#pragma unroll
            for (int p = 0; p < 8; p++) {
                int c = p * 2 + half;
                int o = o0 + c;
                if (O == Opad || o < O) {
                    float v = patch[po * 20 + c];
                    float r;
                    if (MODE == 0)      r = fmaxf(v * __ldg(p0 + o) + __ldg(p1 + o), 0.f);
                    else if (MODE == 1) r = v + __ldg(p0 + o);
                    else                r = v * __ldg(p0 + o) + __ldg(p1 + o);
                    outp[(size_t)(b * O + o) * DHW + pos0 + po] = r;
                }
            }
            __syncwarp();
        }
}

// ================= GroupNorm stats: 2-stage fp32 deterministic =================
__global__ __launch_bounds__(256) void k_gnpart()
{
    __shared__ float rs[256], rs2[256];
    const int grp = blockIdx.x >> 3;     // b*24+gg
    const int slice = blockIdx.x & 7;
    const int tid = threadIdx.x;
    const float4* base = reinterpret_cast<const float4*>(g_w + (size_t)grp * 9 * DHW);
    const int start = slice * 4608;
    float s = 0.f, s2 = 0.f;
#pragma unroll 3
    for (int i = start + tid; i < start + 4608; i += 256) {
        float4 v = base[i];
        s  += (v.x + v.y) + (v.z + v.w);
        s2 += (v.x * v.x + v.y * v.y) + (v.z * v.z + v.w * v.w);
    }
    rs[tid] = s; rs2[tid] = s2; __syncthreads();
    for (int o = 128; o > 0; o >>= 1) {
        if (tid < o) { rs[tid] += rs[tid + o]; rs2[tid] += rs2[tid + o]; }
        __syncthreads();
    }
    if (tid == 0) {
        g_part[blockIdx.x * 2]     = rs[0];
        g_part[blockIdx.x * 2 + 1] = rs2[0];
    }
}
__global__ void k_gnfinal()
{
    const int grp = threadIdx.x;
    if (grp >= 48) return;
    float s = 0.f, s2 = 0.f;
#pragma unroll
    for (int sl = 0; sl < 8; sl++) {
        s  += g_part[(grp * 8 + sl) * 2];
        s2 += g_part[(grp * 8 + sl) * 2 + 1];
    }
    const float n = 9.0f * DHW;
    float mean = s / n;
    float var = s2 / n - mean * mean;
    g_stats[grp * 2] = mean;
    g_stats[grp * 2 + 1] = rsqrtf(var + EPSV);
}

// ================= dynamic 27-tap aggregation + BN4 + swish =================
__global__ __launch_bounds__(128) void k_agg(
    const float* __restrict__ gns, const float* __restrict__ gnb,
    const float* __restrict__ s4, const float* __restrict__ b4)
{
    __shared__ float wn[27 * 4 * 32];   // [tap][y][x]
    __shared__ float vs[12 * 612];      // [c][3z][6y][34x]
    const int bz = blockIdx.z;
    const int b = bz >> 3, gw = bz & 7;
    const int z = blockIdx.y;
    const int y0 = blockIdx.x * 4;
    const int tid = threadIdx.x;
    const int lane = tid & 31, ty = tid >> 5;

    for (int idx = tid; idx < 27 * 128; idx += 128) {
        int tap = idx >> 7; int r = idx & 127;
        int yy = r >> 5, xx = r & 31;
        int ch = gw * 27 + tap;
        int gg = ch / 9;
        float mean = g_stats[(b * 24 + gg) * 2];
        float rstd = g_stats[(b * 24 + gg) * 2 + 1];
        float raw = g_w[(size_t)(b * 216 + ch) * DHW + z * HW + (y0 + yy) * Ww + xx];
        wn[idx] = (raw - mean) * rstd * gns[ch] + gnb[ch];
    }
    __syncthreads();

    float wreg[27];
#pragma unroll
    for (int tap = 0; tap < 27; tap++) wreg[tap] = wn[tap * 128 + ty * 32 + lane];

    for (int cc0 = 0; cc0 < 24; cc0 += 12) {
        __syncthreads();
        for (int idx = tid; idx < 12 * 612; idx += 128) {
            int c = idx / 612; int r = idx - c * 612;
            int zz = r / 204; r -= zz * 204;
            int yy = r / 34; int xx = r - yy * 34;
            int gz = z - 1 + zz, gy = y0 - 1 + yy, gx = xx - 1;
            float v = 0.f;
            if ((unsigned)gz < (unsigned)Dd && (unsigned)gy < (unsigned)Hh &&
                (unsigned)gx < (unsigned)Ww)
                v = g_v[(size_t)(b * DIM + gw * 24 + cc0 + c) * DHW + gz * HW + gy * Ww + gx];
            vs[idx] = v;
        }
        __syncthreads();
        for (int c = 0; c < 12; c++) {
            float a = 0.f;
            const float* vc = vs + c * 612;
#pragma unroll
            for (int dz = 0; dz < 3; dz++)
#pragma unroll
            for (int dy = 0; dy < 3; dy++)
#pragma unroll
            for (int dx = 0; dx < 3; dx++)
                a += wreg[dz * 9 + dy * 3 + dx] *
                     vc[dz * 204 + (ty + dy) * 34 + lane + dx];
            const int ch = gw * 24 + cc0 + c;
            float t = a * s4[ch] + b4[ch];
            float x2v = t / (1.f + expf(-t));
            g_x2[(size_t)(b * DIM + ch) * DHW + z * HW + (y0 + ty) * Ww + lane] = x2v;
        }
    }
}

// ================= global average pool of (x2 + k), float4 =================
__global__ __launch_bounds__(256) void k_gap()
{
    __shared__ float red[256];
    const int row = blockIdx.x;
    const int tid = threadIdx.x;
    const float4* px = reinterpret_cast<const float4*>(g_x2 + (size_t)row * DHW);
    const float4* pk = reinterpret_cast<const float4*>(g_k + (size_t)row * DHW);
    float s = 0.f;
#pragma unroll 4
    for (int i = tid; i < DHW / 4; i += 256) {
        float4 a = px[i]; float4 bq = pk[i];
        s += (a.x + bq.x) + (a.y + bq.y) + (a.z + bq.z) + (a.w + bq.w);
    }
    red[tid] = s; __syncthreads();
    for (int o = 128; o > 0; o >>= 1) {
        if (tid < o) red[tid] += red[tid + o];
        __syncthreads();
    }
    if (tid == 0) g_gap[row] = red[0] * (1.f / DHW);
}

// ================= SE head + softmax attention =================
__global__ __launch_bounds__(192) void k_se(
    const float* __restrict__ w1, const float* __restrict__ bb1,
    const float* __restrict__ bss, const float* __restrict__ bsb,
    const float* __restrict__ w2, const float* __restrict__ bb2)
{
    __shared__ float gap_s[192];
    __shared__ float h1_s[96];
    const int tid = threadIdx.x;
    for (int b = 0; b < Bsz; b++) {
        gap_s[tid] = g_gap[b * DIM + tid];
        __syncthreads();
        if (tid < 96) {
            float a = 0.f;
            for (int i = 0; i < 192; i++) a += w1[tid * 192 + i] * gap_s[i];
            a = (a + bb1[tid]) * bss[tid] + bsb[tid];
            h1_s[tid] = fmaxf(a, 0.f);
        }
        __syncthreads();
        {
            float l0 = bb2[2 * tid], l1 = bb2[2 * tid + 1];
            for (int i = 0; i < 96; i++) {
                float h = h1_s[i];
                l0 += w2[(2 * tid) * 96 + i] * h;
                l1 += w2[(2 * tid + 1) * 96 + i] * h;
            }
            float m = fmaxf(l0, l1);
            float e0 = expf(l0 - m), e1 = expf(l1 - m);
            float inv = 1.f / (e0 + e1);
            g_attn[(b * DIM + tid) * 2] = e0 * inv;
            g_attn[(b * DIM + tid) * 2 + 1] = e1 * inv;
        }
        __syncthreads();
    }
}

// ================= final blend =================
__global__ __launch_bounds__(256) void k_final(float* __restrict__ out)
{
    const int idx = blockIdx.x * 256 + threadIdx.x;
    const int row = idx / (DHW / 4);
    const float a0 = g_attn[row * 2];
    const float a1 = g_attn[row * 2 + 1];
    float4 xv = reinterpret_cast<const float4*>(g_x2)[idx];
    float4 kv = reinterpret_cast<const float4*>(g_k)[idx];
    float4 r;
    r.x = xv.x * a0 + kv.x * a1;
    r.y = xv.y * a0 + kv.y * a1;
    r.z = xv.z * a0 + kv.z * a1;
    r.w = xv.w * a0 + kv.w * a1;
    reinterpret_cast<float4*>(out)[idx] = r;
}

// ================= launch =================
extern "C" void kernel_launch(void* const* d_in, const int* in_sizes, int n_in,
                              void* d_out, int out_size)
{
    const float* x      = (const float*)d_in[0];
    const float* w_key  = (const float*)d_in[1];
    const float* bn1_s  = (const float*)d_in[2];
    const float* bn1_b  = (const float*)d_in[3];
    const float* w_e1   = (const float*)d_in[4];
    const float* bn2_s  = (const float*)d_in[5];
    const float* bn2_b  = (const float*)d_in[6];
    const float* w_e2   = (const float*)d_in[7];
    const float* b_e2   = (const float*)d_in[8];
    const float* gn_s   = (const float*)d_in[9];
    const float* gn_b   = (const float*)d_in[10];
    const float* w_c1   = (const float*)d_in[11];
    const float* bn3_s  = (const float*)d_in[12];
    const float* bn3_b  = (const float*)d_in[13];
    const float* bn4_s  = (const float*)d_in[14];
    const float* bn4_b  = (const float*)d_in[15];
    const float* w_se1  = (const float*)d_in[16];
    const float* b_se1  = (const float*)d_in[17];
    const float* bnse_s = (const float*)d_in[18];
    const float* bnse_b = (const float*)d_in[19];
    const float* w_se2  = (const float*)d_in[20];
    const float* b_se2  = (const float*)d_in[21];
    float* out = (float*)d_out;

    // Reordered so the profiled launch (index 3) is the MODE-0 GEMM.
    k_prep_conv<<<(248832 + 255) / 256, 256>>>(w_key);                        // 0
    k_prep_gemm<<<(95232 + 255) / 256, 256>>>(w_e1, w_e2, w_c1);              // 1
    k_conv_mma<<<dim3(4, 16, 8), 256>>>(x, bn1_s, bn1_b);                     // 2
    k_gemm_mma<96, 96, 384, 0><<<dim3(128, 2), 256>>>(x, bn2_s, bn2_b);       // 3 (captured: e)
    k_gemm_mma<192, 192, 192, 2><<<dim3(128, 2), 256>>>(x, bn3_s, bn3_b);     // 4 (v)
    k_gemm_mma<216, 224, 96, 1><<<dim3(128, 2), 256>>>(x, b_e2, b_e2);        // 5 (w)
    k_gnpart<<<48 * 8, 256>>>();
    k_gnfinal<<<1, 64>>>();
    k_agg<<<dim3(8, 16, 16), 128>>>(gn_s, gn_b, bn4_s, bn4_b);
    k_gap<<<Bsz * DIM, 256>>>();
    k_se<<<1, 192>>>(w_se1, b_se1, bnse_s, bnse_b, w_se2, b_se2);
    k_final<<<(Bsz * DIM * DHW / 4) / 256, 256>>>(out);
}

// round 13
// speedup vs baseline: 1.1222x; 1.0620x over previous
#include <cuda_runtime.h>
#include <math.h>
#include <cstdint>
#include <mma.h>

using namespace nvcuda;

#define Bsz 2
#define DIM 192
#define Dd 16
#define Hh 32
#define Ww 32
#define HW 1024
#define DHW 16384
#define EPSV 1e-5f

// ---------------- scratch (device globals; no allocations allowed) ----------------
__device__ float g_k  [Bsz * DIM * DHW];     // key conv output (post BN+ReLU)
__device__ float g_e  [Bsz * 96  * DHW];     // embed 1
__device__ float g_w  [Bsz * 216 * DHW];     // dyn weights pre-GN (biased)
__device__ float g_v  [Bsz * DIM * DHW];     // value conv output
__device__ float g_x2 [Bsz * DIM * DHW];     // aggregated + swish
__device__ float g_stats[Bsz * 24 * 2];      // per (b, gn-group): mean, rstd
__device__ float g_part [Bsz * 24 * 8 * 2];  // partial sums (deterministic 2-stage)
__device__ float g_gap[Bsz * DIM];
__device__ float g_attn[Bsz * DIM * 2];
// pre-transposed tf32 weights (accessed ONLY from device code!)
__device__ float g_wconv[4 * 27 * 48 * 48];  // [g][tap][ci][co]
__device__ float g_we1t[384 * 96];           // [i][o]
__device__ float g_we2t[96 * 224];           // [i][o] (216 padded to 224 w/ zeros)
__device__ float g_wc1t[192 * 192];          // [i][o]

// ================= helpers =================
__device__ __forceinline__ float f2tf(float f) {
    uint32_t u;
    asm("cvt.rna.tf32.f32 %0, %1;" : "=r"(u) : "f"(f));
    return __uint_as_float(u);
}

// ================= prep kernels: transpose + tf32-convert weights =================
__global__ __launch_bounds__(256) void k_prep_gemm(
    const float* __restrict__ w_e1, const float* __restrict__ w_e2,
    const float* __restrict__ w_c1)
{
    int id = blockIdx.x * 256 + threadIdx.x;
    if (id < 36864) {
        int i = id / 96, o = id % 96;
        g_we1t[id] = f2tf(w_e1[o * 384 + i]);
    } else if (id < 36864 + 21504) {
        int r = id - 36864;
        int i = r / 224, o = r % 224;
        g_we2t[r] = (o < 216) ? f2tf(w_e2[o * 96 + i]) : 0.f;
    } else if (id < 36864 + 21504 + 36864) {
        int r = id - 36864 - 21504;
        int i = r / 192, o = r % 192;
        g_wc1t[r] = f2tf(w_c1[o * 192 + i]);
    }
}
__global__ __launch_bounds__(256) void k_prep_conv(const float* __restrict__ w_key)
{
    int id = blockIdx.x * 256 + threadIdx.x;
    if (id < 248832) {
        int co = id % 48;
        int ci = (id / 48) % 48;
        int tap = (id / 2304) % 27;
        int g = id / 62208;
        g_wconv[id] = f2tf(w_key[((size_t)(g * 48 + co) * 48 + ci) * 27 + tap]);
    }
}

// ================= conv 3x3x3 grouped, implicit GEMM via wmma tf32 (v3) =================
// block: 256 thr = 8 warps; tile 512 pos (2z x 8y x 32x) x 48 co; one wave (256 blocks).
// warp w owns m-tiles {w, w+8, w+16, w+24} x 3 n-tiles -> 24 HMMA per 7 frag loads.
#define HSTR2 1368  // halo ci-stride in floats (4 zz * 340 + 8 pad)
#define WSTR 56     // weight ci-stride
__global__ __launch_bounds__(256, 2) void k_conv_mma(
    const float* __restrict__ x, const float* __restrict__ s1,
    const float* __restrict__ b1)
{
    extern __shared__ float smem[];        // 8*HSTR2 + 9*8*WSTR = 14976 floats
    float* hs = smem;                      // halo: [ci][zz*340 + yy*34 + xx]
    float* ws = smem + 8 * HSTR2;          // weights: [t9][ci][co]

    const int tid = threadIdx.x;
    const int warp = tid >> 5;
    const int bz = blockIdx.z;
    const int b = bz >> 2, g = bz & 3;
    const int z0 = blockIdx.y * 2;
    const int y0 = blockIdx.x * 8;

    wmma::fragment<wmma::accumulator, 16, 16, 8, float> acc[4][3];
#pragma unroll
    for (int r = 0; r < 4; r++)
#pragma unroll
        for (int j = 0; j < 3; j++) wmma::fill_fragment(acc[r][j], 0.f);

    const float* xg = x + (size_t)(b * DIM + g * 48) * DHW;
    const float* wg = g_wconv + (size_t)g * 27 * 48 * 48;

    for (int ci0 = 0; ci0 < 48; ci0 += 8) {
        __syncthreads();
        // stage halo: 8 ci x (4z x 10y x 34x), tf32-rounded
        for (int idx = tid; idx < 10880; idx += 256) {
            int ci = idx / 1360, r = idx - ci * 1360;
            int zz = r / 340; r -= zz * 340;
            int yy = r / 34;  int xx = r - yy * 34;
            int gz = z0 - 1 + zz, gy = y0 - 1 + yy, gx = xx - 1;
            float v = 0.f;
            if ((unsigned)gz < (unsigned)Dd && (unsigned)gy < (unsigned)Hh &&
                (unsigned)gx < (unsigned)Ww)
                v = xg[(size_t)(ci0 + ci) * DHW + gz * HW + gy * Ww + gx];
            hs[ci * HSTR2 + zz * 340 + yy * 34 + xx] = f2tf(v);
        }
        for (int dz = 0; dz < 3; dz++) {
            __syncthreads();
            // stage weights for the 9 taps of this dz: [t9][ci][co]
            for (int idx = tid; idx < 9 * 8 * 48; idx += 256) {
                int t9 = idx / 384, r = idx - t9 * 384;
                int ci = r / 48, co = r - ci * 48;
                ws[t9 * (8 * WSTR) + ci * WSTR + co] =
                    wg[((size_t)(dz * 9 + t9) * 48 + ci0 + ci) * 48 + co];
            }
            __syncthreads();
#pragma unroll
            for (int t9 = 0; t9 < 9; t9++) {
                const int dy = t9 / 3, dx = t9 % 3;
                wmma::fragment<wmma::matrix_b, 16, 16, 8,
                               wmma::precision::tf32, wmma::row_major> bf[3];
#pragma unroll
                for (int j = 0; j < 3; j++)
                    wmma::load_matrix_sync(bf[j], ws + t9 * (8 * WSTR) + j * 16, WSTR);
#pragma unroll
                for (int r = 0; r < 4; r++) {
                    const int m = warp + 8 * r;
                    const int mzz = m >> 4, myy = (m >> 1) & 7, xh = m & 1;
                    const float* aptr = hs + (mzz + dz) * 340 +
                                        (myy + dy) * 34 + xh * 16 + dx;
                    wmma::fragment<wmma::matrix_a, 16, 16, 8,
                                   wmma::precision::tf32, wmma::col_major> af;
                    wmma::load_matrix_sync(af, aptr, HSTR2);
#pragma unroll
                    for (int j = 0; j < 3; j++)
                        wmma::mma_sync(acc[r][j], af, bf[j], acc[r][j]);
                }
            }
        }
    }

    // ---- epilogue: two z-plane halves; stage 256x48 in smem, BN+ReLU store ----
#pragma unroll
    for (int half = 0; half < 2; half++) {
        __syncthreads();
#pragma unroll
        for (int r2 = 0; r2 < 2; r2++) {
            const int r = half * 2 + r2;
            const int posL = (warp + 8 * r2) * 16;   // (m & 15) * 16
#pragma unroll
            for (int j = 0; j < 3; j++)
                wmma::store_matrix_sync(smem + posL * 48 + j * 16,
                                        acc[r][j], 48, wmma::mem_row_major);
        }
        __syncthreads();
        for (int i = tid; i < 12288; i += 256) {
            int ch = i >> 8, pos = i & 255;
            int chg = g * 48 + ch;
            float v = smem[pos * 48 + ch] * __ldg(s1 + chg) + __ldg(b1 + chg);
            g_k[(size_t)(b * DIM + chg) * DHW + (z0 + half) * HW + y0 * Ww + pos] =
                fmaxf(v, 0.f);
        }
    }
}

// ================= 1x1 conv GEMM via wmma tf32 =================
// D[128 pos, Opad] = A[pos, I] x Wt[I, Opad].  channel-major in/out.
// MODE 0: e = relu(bn2(.)) from concat(x, g_k), O=96,  I=384 -> g_e
// MODE 1: w = . + b_e2 from g_e,                O=216, I=96  -> g_w
// MODE 2: v = bn3(.) from x,                    O=192, I=192 -> g_v
template <int O, int Opad, int I, int MODE>
__global__ __launch_bounds__(256) void k_gemm_mma(
    const float* __restrict__ x,
    const float* __restrict__ p0, const float* __restrict__ p1)
{
    constexpr int ASTR = 136;
    constexpr int BSTR = Opad + 8;
    constexpr int NT = Opad / 32;       // n-tiles per warp
    __shared__ float As[32 * ASTR];     // also reused as epilogue patches
    __shared__ float Bs[32 * BSTR];

    const float* __restrict__ Wt =
        (MODE == 0) ? g_we1t : (MODE == 1) ? g_we2t : g_wc1t;

    const int tid = threadIdx.x;
    const int lane = tid & 31, warp = tid >> 5;
    const int mw = warp & 3, nw = warp >> 2;
    const int b = blockIdx.y;
    const int pbase = blockIdx.x * 128;

    wmma::fragment<wmma::accumulator, 16, 16, 8, float> acc[2][NT];
#pragma unroll
    for (int mt = 0; mt < 2; mt++)
#pragma unroll
        for (int j = 0; j < NT; j++) wmma::fill_fragment(acc[mt][j], 0.f);

    for (int i0 = 0; i0 < I; i0 += 32) {
        // stage A: 32 k x 128 pos (tf32)
#pragma unroll
        for (int r = 0; r < 4; r++) {
            int idx = tid + r * 256;
            int k = idx >> 5, p4 = idx & 31;
            int ch = i0 + k;
            const float* srow;
            if (MODE == 0)
                srow = (ch < DIM) ? x + (size_t)(b * DIM + ch) * DHW
                                  : g_k + (size_t)(b * DIM + ch - DIM) * DHW;
            else if (MODE == 1)
                srow = g_e + (size_t)(b * 96 + ch) * DHW;
            else
                srow = x + (size_t)(b * DIM + ch) * DHW;
            float4 v = *reinterpret_cast<const float4*>(srow + pbase + p4 * 4);
            float* dst = As + k * ASTR + p4 * 4;
            dst[0] = f2tf(v.x); dst[1] = f2tf(v.y);
            dst[2] = f2tf(v.z); dst[3] = f2tf(v.w);
        }
        // stage B: 32 k x Opad (already tf32)
        for (int idx = tid; idx < 32 * (Opad / 4); idx += 256) {
            int k = idx / (Opad / 4), q4 = idx - k * (Opad / 4);
            float4 wv = *reinterpret_cast<const float4*>(
                Wt + (size_t)(i0 + k) * Opad + q4 * 4);
            float* dst = Bs + k * BSTR + q4 * 4;
            dst[0] = wv.x; dst[1] = wv.y; dst[2] = wv.z; dst[3] = wv.w;
        }
        __syncthreads();
#pragma unroll
        for (int ks = 0; ks < 4; ks++) {
            wmma::fragment<wmma::matrix_a, 16, 16, 8,
                           wmma::precision::tf32, wmma::col_major> af[2];
#pragma unroll
            for (int mt = 0; mt < 2; mt++)
                wmma::load_matrix_sync(af[mt],
                    As + ks * 8 * ASTR + mw * 32 + mt * 16, ASTR);
#pragma unroll
            for (int j = 0; j < NT; j++) {
                wmma::fragment<wmma::matrix_b, 16, 16, 8,
                               wmma::precision::tf32, wmma::row_major> bf;
                wmma::load_matrix_sync(bf,
                    Bs + ks * 8 * BSTR + (nw * NT + j) * 16, BSTR);
                wmma::mma_sync(acc[0][j], af[0], bf, acc[0][j]);
                wmma::mma_sync(acc[1][j], af[1], bf, acc[1][j]);
            }
        }
        __syncthreads();
    }

    // ---- epilogue via per-warp smem patch (reuse As) ----
    float* patch = As + warp * 320;     // 16 x 20
    float* outp = (MODE == 0) ? g_e : (MODE == 1) ? g_w : g_v;
#pragma unroll
    for (int mt = 0; mt < 2; mt++)
#pragma unroll
        for (int j = 0; j < NT; j++) {
            wmma::store_matrix_sync(patch, acc[mt][j], 20, wmma::mem_row_major);
            __syncwarp();
            int pos0 = pbase + mw * 32 + mt * 16;
            int o0 = (nw * NT + j) * 16;
            int po = lane & 15, half = lane >> 4;
#pragma unroll
            for (int p = 0; p < 8; p++) {
                int c = p * 2 + half;
                int o = o0 + c;
                if (O == Opad || o < O) {
                    float v = patch[po * 20 + c];
                    float r;
                    if (MODE == 0)      r = fmaxf(v * __ldg(p0 + o) + __ldg(p1 + o), 0.f);
                    else if (MODE == 1) r = v + __ldg(p0 + o);
                    else                r = v * __ldg(p0 + o) + __ldg(p1 + o);
                    outp[(size_t)(b * O + o) * DHW + pos0 + po] = r;
                }
            }
            __syncwarp();
        }
}

// ================= GroupNorm stats: 2-stage fp32 deterministic =================
__global__ __launch_bounds__(256) void k_gnpart()
{
    __shared__ float rs[256], rs2[256];
    const int grp = blockIdx.x >> 3;     // b*24+gg
    const int slice = blockIdx.x & 7;
    const int tid = threadIdx.x;
    const float4* base = reinterpret_cast<const float4*>(g_w + (size_t)grp * 9 * DHW);
    const int start = slice * 4608;
    float s = 0.f, s2 = 0.f;
#pragma unroll 3
    for (int i = start + tid; i < start + 4608; i += 256) {
        float4 v = base[i];
        s  += (v.x + v.y) + (v.z + v.w);
        s2 += (v.x * v.x + v.y * v.y) + (v.z * v.z + v.w * v.w);
    }
    rs[tid] = s; rs2[tid] = s2; __syncthreads();
    for (int o = 128; o > 0; o >>= 1) {
        if (tid < o) { rs[tid] += rs[tid + o]; rs2[tid] += rs2[tid + o]; }
        __syncthreads();
    }
    if (tid == 0) {
        g_part[blockIdx.x * 2]     = rs[0];
        g_part[blockIdx.x * 2 + 1] = rs2[0];
    }
}
__global__ void k_gnfinal()
{
    const int grp = threadIdx.x;
    if (grp >= 48) return;
    float s = 0.f, s2 = 0.f;
#pragma unroll
    for (int sl = 0; sl < 8; sl++) {
        s  += g_part[(grp * 8 + sl) * 2];
        s2 += g_part[(grp * 8 + sl) * 2 + 1];
    }
    const float n = 9.0f * DHW;
    float mean = s / n;
    float var = s2 / n - mean * mean;
    g_stats[grp * 2] = mean;
    g_stats[grp * 2 + 1] = rsqrtf(var + EPSV);
}

// ================= dynamic 27-tap aggregation + BN4 + swish =================
__global__ __launch_bounds__(128) void k_agg(
    const float* __restrict__ gns, const float* __restrict__ gnb,
    const float* __restrict__ s4, const float* __restrict__ b4)
{
    __shared__ float wn[27 * 4 * 32];   // [tap][y][x]
    __shared__ float vs[12 * 612];      // [c][3z][6y][34x]
    const int bz = blockIdx.z;
    const int b = bz >> 3, gw = bz & 7;
    const int z = blockIdx.y;
    const int y0 = blockIdx.x * 4;
    const int tid = threadIdx.x;
    const int lane = tid & 31, ty = tid >> 5;

    for (int idx = tid; idx < 27 * 128; idx += 128) {
        int tap = idx >> 7; int r = idx & 127;
        int yy = r >> 5, xx = r & 31;
        int ch = gw * 27 + tap;
        int gg = ch / 9;
        float mean = g_stats[(b * 24 + gg) * 2];
        float rstd = g_stats[(b * 24 + gg) * 2 + 1];
        float raw = g_w[(size_t)(b * 216 + ch) * DHW + z * HW + (y0 + yy) * Ww + xx];
        wn[idx] = (raw - mean) * rstd * gns[ch] + gnb[ch];
    }
    __syncthreads();

    float wreg[27];
#pragma unroll
    for (int tap = 0; tap < 27; tap++) wreg[tap] = wn[tap * 128 + ty * 32 + lane];

    for (int cc0 = 0; cc0 < 24; cc0 += 12) {
        __syncthreads();
        for (int idx = tid; idx < 12 * 612; idx += 128) {
            int c = idx / 612; int r = idx - c * 612;
            int zz = r / 204; r -= zz * 204;
            int yy = r / 34; int xx = r - yy * 34;
            int gz = z - 1 + zz, gy = y0 - 1 + yy, gx = xx - 1;
            float v = 0.f;
            if ((unsigned)gz < (unsigned)Dd && (unsigned)gy < (unsigned)Hh &&
                (unsigned)gx < (unsigned)Ww)
                v = g_v[(size_t)(b * DIM + gw * 24 + cc0 + c) * DHW + gz * HW + gy * Ww + gx];
            vs[idx] = v;
        }
        __syncthreads();
        for (int c = 0; c < 12; c++) {
            float a = 0.f;
            const float* vc = vs + c * 612;
#pragma unroll
            for (int dz = 0; dz < 3; dz++)
#pragma unroll
            for (int dy = 0; dy < 3; dy++)
#pragma unroll
            for (int dx = 0; dx < 3; dx++)
                a += wreg[dz * 9 + dy * 3 + dx] *
                     vc[dz * 204 + (ty + dy) * 34 + lane + dx];
            const int ch = gw * 24 + cc0 + c;
            float t = a * s4[ch] + b4[ch];
            float x2v = t / (1.f + expf(-t));
            g_x2[(size_t)(b * DIM + ch) * DHW + z * HW + (y0 + ty) * Ww + lane] = x2v;
        }
    }
}

// ================= global average pool of (x2 + k), float4 =================
__global__ __launch_bounds__(256) void k_gap()
{
    __shared__ float red[256];
    const int row = blockIdx.x;
    const int tid = threadIdx.x;
    const float4* px = reinterpret_cast<const float4*>(g_x2 + (size_t)row * DHW);
    const float4* pk = reinterpret_cast<const float4*>(g_k + (size_t)row * DHW);
    float s = 0.f;
#pragma unroll 4
    for (int i = tid; i < DHW / 4; i += 256) {
        float4 a = px[i]; float4 bq = pk[i];
        s += (a.x + bq.x) + (a.y + bq.y) + (a.z + bq.z) + (a.w + bq.w);
    }
    red[tid] = s; __syncthreads();
    for (int o = 128; o > 0; o >>= 1) {
        if (tid < o) red[tid] += red[tid + o];
        __syncthreads();
    }
    if (tid == 0) g_gap[row] = red[0] * (1.f / DHW);
}

// ================= SE head + softmax attention =================
__global__ __launch_bounds__(192) void k_se(
    const float* __restrict__ w1, const float* __restrict__ bb1,
    const float* __restrict__ bss, const float* __restrict__ bsb,
    const float* __restrict__ w2, const float* __restrict__ bb2)
{
    __shared__ float gap_s[192];
    __shared__ float h1_s[96];
    const int tid = threadIdx.x;
    for (int b = 0; b < Bsz; b++) {
        gap_s[tid] = g_gap[b * DIM + tid];
        __syncthreads();
        if (tid < 96) {
            float a = 0.f;
            for (int i = 0; i < 192; i++) a += w1[tid * 192 + i] * gap_s[i];
            a = (a + bb1[tid]) * bss[tid] + bsb[tid];
            h1_s[tid] = fmaxf(a, 0.f);
        }
        __syncthreads();
        {
            float l0 = bb2[2 * tid], l1 = bb2[2 * tid + 1];
            for (int i = 0; i < 96; i++) {
                float h = h1_s[i];
                l0 += w2[(2 * tid) * 96 + i] * h;
                l1 += w2[(2 * tid + 1) * 96 + i] * h;
            }
            float m = fmaxf(l0, l1);
            float e0 = expf(l0 - m), e1 = expf(l1 - m);
            float inv = 1.f / (e0 + e1);
            g_attn[(b * DIM + tid) * 2] = e0 * inv;
            g_attn[(b * DIM + tid) * 2 + 1] = e1 * inv;
        }
        __syncthreads();
    }
}

// ================= final blend =================
__global__ __launch_bounds__(256) void k_final(float* __restrict__ out)
{
    const int idx = blockIdx.x * 256 + threadIdx.x;
    const int row = idx / (DHW / 4);
    const float a0 = g_attn[row * 2];
    const float a1 = g_attn[row * 2 + 1];
    float4 xv = reinterpret_cast<const float4*>(g_x2)[idx];
    float4 kv = reinterpret_cast<const float4*>(g_k)[idx];
    float4 r;
    r.x = xv.x * a0 + kv.x * a1;
    r.y = xv.y * a0 + kv.y * a1;
    r.z = xv.z * a0 + kv.z * a1;
    r.w = xv.w * a0 + kv.w * a1;
    reinterpret_cast<float4*>(out)[idx] = r;
}

// ================= launch =================
extern "C" void kernel_launch(void* const* d_in, const int* in_sizes, int n_in,
                              void* d_out, int out_size)
{
    const float* x      = (const float*)d_in[0];
    const float* w_key  = (const float*)d_in[1];
    const float* bn1_s  = (const float*)d_in[2];
    const float* bn1_b  = (const float*)d_in[3];
    const float* w_e1   = (const float*)d_in[4];
    const float* bn2_s  = (const float*)d_in[5];
    const float* bn2_b  = (const float*)d_in[6];
    const float* w_e2   = (const float*)d_in[7];
    const float* b_e2   = (const float*)d_in[8];
    const float* gn_s   = (const float*)d_in[9];
    const float* gn_b   = (const float*)d_in[10];
    const float* w_c1   = (const float*)d_in[11];
    const float* bn3_s  = (const float*)d_in[12];
    const float* bn3_b  = (const float*)d_in[13];
    const float* bn4_s  = (const float*)d_in[14];
    const float* bn4_b  = (const float*)d_in[15];
    const float* w_se1  = (const float*)d_in[16];
    const float* b_se1  = (const float*)d_in[17];
    const float* bnse_s = (const float*)d_in[18];
    const float* bnse_b = (const float*)d_in[19];
    const float* w_se2  = (const float*)d_in[20];
    const float* b_se2  = (const float*)d_in[21];
    float* out = (float*)d_out;

    const int conv_smem = (8 * HSTR2 + 9 * 8 * WSTR) * sizeof(float);  // 59904 B
    cudaFuncSetAttribute(k_conv_mma,
                         cudaFuncAttributeMaxDynamicSharedMemorySize, conv_smem);

    // order chosen so the profiled launch (index 3) is the new conv
    k_prep_conv<<<(248832 + 255) / 256, 256>>>(w_key);                        // 0
    k_prep_gemm<<<(95232 + 255) / 256, 256>>>(w_e1, w_e2, w_c1);              // 1
    k_gemm_mma<192, 192, 192, 2><<<dim3(128, 2), 256>>>(x, bn3_s, bn3_b);     // 2 (v)
    k_conv_mma<<<dim3(4, 8, 8), 256, conv_smem>>>(x, bn1_s, bn1_b);           // 3 (captured)
    k_gemm_mma<96, 96, 384, 0><<<dim3(128, 2), 256>>>(x, bn2_s, bn2_b);       // 4 (e)
    k_gemm_mma<216, 224, 96, 1><<<dim3(128, 2), 256>>>(x, b_e2, b_e2);        // 5 (w)
    k_gnpart<<<48 * 8, 256>>>();
    k_gnfinal<<<1, 64>>>();
    k_agg<<<dim3(8, 16, 16), 128>>>(gn_s, gn_b, bn4_s, bn4_b);
    k_gap<<<Bsz * DIM, 256>>>();
    k_se<<<1, 192>>>(w_se1, b_se1, bnse_s, bnse_b, w_se2, b_se2);
    k_final<<<(Bsz * DIM * DHW / 4) / 256, 256>>>(out);
}